// round 4
// baseline (speedup 1.0000x reference)
#include <cuda_runtime.h>

#define NN 64
#define CC 128
#define HH 64
#define WW 64
#define HID 8

// Scratch (device globals). All fully rewritten every call -> deterministic.
__device__ float g_gap[NN][CC];          // per-(n,c) spatial mean
__device__ float g_pool[NN][CC][16];     // per-(n,c) 4x4 pooled means
__device__ float g_sp[NN][9];
__device__ float g_co[NN][CC];
__device__ float g_ci[NN][CC];
__device__ float g_z[NN][HH][WW];        // ci-weighted channel reduction

// ---------------------------------------------------------------------------
// Kernel A: per (n,c) plane -> spatial mean + 16 pooled means.
// One block per (n,c), 256 threads; thread t = (row r=t/4, quarter q=t%4)
// sums 16 contiguous floats. Pool p = (r/16)*4 + q.
// ---------------------------------------------------------------------------
__global__ void kA_reduce(const float* __restrict__ x) {
    int nc = blockIdx.x;               // n*CC + c
    int t  = threadIdx.x;              // 0..255
    int r  = t >> 2;                   // row 0..63
    int q  = t & 3;                    // quarter 0..3

    const float4* xp = (const float4*)(x + (size_t)nc * (HH * WW));
    float s = 0.f;
#pragma unroll
    for (int j = 0; j < 4; ++j) {
        float4 v = xp[r * 16 + q * 4 + j];
        s += (v.x + v.y) + (v.z + v.w);
    }

    __shared__ float part[256];
    __shared__ float spool[16];
    part[t] = s;
    __syncthreads();

    int n = nc >> 7;
    int c = nc & 127;
    if (t < 16) {
        int pr = t >> 2, pq = t & 3;
        float ps = 0.f;
#pragma unroll
        for (int rr = 0; rr < 16; ++rr)
            ps += part[(pr * 16 + rr) * 4 + pq];
        spool[t] = ps;
        g_pool[n][c][t] = ps * (1.f / 256.f);
    }
    __syncthreads();
    if (t == 0) {
        float tot = 0.f;
#pragma unroll
        for (int p = 0; p < 16; ++p) tot += spool[p];
        g_gap[n][c] = tot * (1.f / (HH * WW));
    }
}

// ---------------------------------------------------------------------------
// Kernel B: per-sample MLPs. One block per n, 128 threads.
// ---------------------------------------------------------------------------
__global__ void kB_mlp(const float* __restrict__ W_sp, const float* __restrict__ b_sp,
                       const float* __restrict__ W_o1, const float* __restrict__ b_o1,
                       const float* __restrict__ W_o2, const float* __restrict__ b_o2,
                       const float* __restrict__ W_i1, const float* __restrict__ b_i1,
                       const float* __restrict__ W_i2, const float* __restrict__ b_i2) {
    int n = blockIdx.x;
    int t = threadIdx.x;               // 0..127

    __shared__ float sg[CC];
    __shared__ float sxs[16];
    __shared__ float sho[HID];
    __shared__ float shi[HID];

    sg[t] = g_gap[n][t];
    if (t < 16) {
        float s = 0.f;
        for (int c = 0; c < CC; ++c) s += g_pool[n][c][t];
        sxs[t] = s * (1.f / CC);
    }
    __syncthreads();

    if (t < HID) {
        float a = b_o1[t];
        float b = b_i1[t];
        for (int c = 0; c < CC; ++c) {
            a += sg[c] * W_o1[c * HID + t];
            b += sg[c] * W_i1[c * HID + t];
        }
        sho[t] = fmaxf(a, 0.f);
        shi[t] = fmaxf(b, 0.f);
    }
    __syncthreads();

    float a = b_o2[t];
    float b = b_i2[t];
#pragma unroll
    for (int j = 0; j < HID; ++j) {
        a += sho[j] * W_o2[j * CC + t];
        b += shi[j] * W_i2[j * CC + t];
    }
    g_co[n][t] = a;
    g_ci[n][t] = b;

    if (t < 9) {
        float s = b_sp[t];
#pragma unroll
        for (int p = 0; p < 16; ++p) s += sxs[p] * W_sp[p * 9 + t];
        g_sp[n][t] = s;
    }
}

// ---------------------------------------------------------------------------
// Kernel C: z[n,h,w] = sum_i ci[n,i] * x[n,i,h,w]
// grid (H, N) = 4096 blocks, 64 threads = one output row. 8192 warps for
// latency hiding; unroll 16 for deeper MLP.
// ---------------------------------------------------------------------------
__global__ void kC_chanreduce(const float* __restrict__ x) {
    int h = blockIdx.x;
    int n = blockIdx.y;
    int w = threadIdx.x;               // 0..63

    __shared__ float sci[CC];
    sci[w]      = g_ci[n][w];
    sci[w + 64] = g_ci[n][w + 64];
    __syncthreads();

    const float* xp = x + ((size_t)n * CC) * (HH * WW) + h * WW + w;
    float acc = 0.f;
#pragma unroll 16
    for (int i = 0; i < CC; ++i)
        acc += sci[i] * xp[(size_t)i * (HH * WW)];
    g_z[n][h][w] = acc;
}

// ---------------------------------------------------------------------------
// Fused kernel DE: per block (row-chunk, n, o-group):
//   1) stage z rows [r0-1, r0+8] in smem (zero-padded)
//   2) compute t tile = conv3x3(z, sp) for 8 rows (recomputed per o-group;
//      ~4.6K FMAs, free vs the 33.5 KB of stores this block owns)
//   3) sweep this block's 32 output channels: out[n,o,rows,:] = co[n,o] * t
// grid (8, NN, 4) = 2048 blocks (13x148+124: balanced waves), 256 threads.
// ---------------------------------------------------------------------------
__global__ void kDE_convscale(float4* __restrict__ out) {
    int chunk = blockIdx.x;            // 0..7 -> output rows [chunk*8, +8)
    int n     = blockIdx.y;
    int ogrp  = blockIdx.z;            // 0..3 -> o in [ogrp*32, +32)
    int t     = threadIdx.x;           // 0..255

    __shared__ float sz[10][WW];       // rows r0-1 .. r0+8
    __shared__ float st[8][WW];        // conv result tile
    __shared__ float sco[32];
    __shared__ float ssp[9];

    int r0 = chunk * 8;

    // stage z rows with halo: 10 rows x 16 quads = 160 quads (L2-hot)
    if (t < 160) {
        int rr = t >> 4, qq = t & 15;
        int h = r0 - 1 + rr;
        float4 v = make_float4(0.f, 0.f, 0.f, 0.f);
        if (h >= 0 && h < HH)
            v = ((const float4*)g_z)[(n * HH + h) * 16 + qq];
        ((float4*)&sz[rr][0])[qq] = v;
    }
    if (t >= 192 && t < 224) sco[t - 192] = g_co[n][ogrp * 32 + (t - 192)];
    if (t >= 240 && t < 249) ssp[t - 240] = g_sp[n][t - 240];
    __syncthreads();

    // conv: 8*64 = 512 outputs, 2 per thread
#pragma unroll
    for (int k = 0; k < 2; ++k) {
        int p = t + k * 256;           // 0..511
        int h = p >> 6, w = p & 63;    // local row 0..7
        float acc = 0.f;
#pragma unroll
        for (int kh = 0; kh < 3; ++kh) {
#pragma unroll
            for (int kw = 0; kw < 3; ++kw) {
                int ww = w + kw - 1;
                if (ww >= 0 && ww < WW)
                    acc += ssp[kh * 3 + kw] * sz[h + kh][ww];
            }
        }
        st[h][w] = acc;
    }
    __syncthreads();

    // broadcast-scale write: thread owns one quad of the tile and one of two
    // 16-channel subgroups; 16 float4 stores, independent (full ILP).
    int q  = t & 127;                  // quad within tile
    int os = t >> 7;                   // 0 or 1 -> 16-channel subgroup
    float4 v = ((const float4*)st)[q];
    int rr = q >> 4, qq = q & 15;

    int o0 = ogrp * 32 + os * 16;
    size_t base = ((size_t)n * CC + o0) * (HH * WW / 4)
                + (size_t)(r0 + rr) * 16 + qq;
#pragma unroll 4
    for (int o = 0; o < 16; ++o) {
        float s = sco[os * 16 + o];
        float4 ov;
        ov.x = v.x * s; ov.y = v.y * s; ov.z = v.z * s; ov.w = v.w * s;
        out[base + (size_t)o * (HH * WW / 4)] = ov;
    }
}

// ---------------------------------------------------------------------------
extern "C" void kernel_launch(void* const* d_in, const int* in_sizes, int n_in,
                              void* d_out, int out_size) {
    const float* x    = (const float*)d_in[0];
    const float* W_sp = (const float*)d_in[1];
    const float* b_sp = (const float*)d_in[2];
    const float* W_o1 = (const float*)d_in[3];
    const float* b_o1 = (const float*)d_in[4];
    const float* W_o2 = (const float*)d_in[5];
    const float* b_o2 = (const float*)d_in[6];
    const float* W_i1 = (const float*)d_in[7];
    const float* b_i1 = (const float*)d_in[8];
    const float* W_i2 = (const float*)d_in[9];
    const float* b_i2 = (const float*)d_in[10];

    kA_reduce<<<NN * CC, 256>>>(x);
    kB_mlp<<<NN, CC>>>(W_sp, b_sp, W_o1, b_o1, W_o2, b_o2,
                       W_i1, b_i1, W_i2, b_i2);
    {
        dim3 g(HH, NN);
        kC_chanreduce<<<g, WW>>>(x);
    }
    {
        dim3 g(8, NN, 4);
        kDE_convscale<<<g, 256>>>((float4*)d_out);
    }
}

// round 5
// speedup vs baseline: 1.0675x; 1.0675x over previous
#include <cuda_runtime.h>

#define NN 64
#define CC 128
#define HH 64
#define WW 64
#define HID 8

// Scratch (device globals). All fully rewritten every call -> deterministic.
__device__ float g_gap[NN][CC];          // per-(n,c) spatial mean
__device__ float g_pool[NN][CC][16];     // per-(n,c) 4x4 pooled means
__device__ float g_sp[NN][9];
__device__ float g_co[NN][CC];
__device__ float g_ci[NN][CC];
__device__ float g_z[NN][HH][WW];        // ci-weighted channel reduction

// ---------------------------------------------------------------------------
// Kernel A: per (n,c) plane -> spatial mean + 16 pooled means.
// One block per (n,c), 256 threads. Normal (caching) loads: we WANT x to be
// L2-resident when kC re-reads it.
// ---------------------------------------------------------------------------
__global__ void kA_reduce(const float* __restrict__ x) {
    int nc = blockIdx.x;               // n*CC + c
    int t  = threadIdx.x;              // 0..255
    int r  = t >> 2;                   // row 0..63
    int q  = t & 3;                    // quarter 0..3

    const float4* xp = (const float4*)(x + (size_t)nc * (HH * WW));
    float s = 0.f;
#pragma unroll
    for (int j = 0; j < 4; ++j) {
        float4 v = xp[r * 16 + q * 4 + j];
        s += (v.x + v.y) + (v.z + v.w);
    }

    __shared__ float part[256];
    __shared__ float spool[16];
    part[t] = s;
    __syncthreads();

    int n = nc >> 7;
    int c = nc & 127;
    if (t < 16) {
        int pr = t >> 2, pq = t & 3;
        float ps = 0.f;
#pragma unroll
        for (int rr = 0; rr < 16; ++rr)
            ps += part[(pr * 16 + rr) * 4 + pq];
        spool[t] = ps;
        g_pool[n][c][t] = ps * (1.f / 256.f);
    }
    __syncthreads();
    if (t == 0) {
        float tot = 0.f;
#pragma unroll
        for (int p = 0; p < 16; ++p) tot += spool[p];
        g_gap[n][c] = tot * (1.f / (HH * WW));
    }
}

// ---------------------------------------------------------------------------
// Kernel B: per-sample MLPs. One block per n, 128 threads.
// ---------------------------------------------------------------------------
__global__ void kB_mlp(const float* __restrict__ W_sp, const float* __restrict__ b_sp,
                       const float* __restrict__ W_o1, const float* __restrict__ b_o1,
                       const float* __restrict__ W_o2, const float* __restrict__ b_o2,
                       const float* __restrict__ W_i1, const float* __restrict__ b_i1,
                       const float* __restrict__ W_i2, const float* __restrict__ b_i2) {
    int n = blockIdx.x;
    int t = threadIdx.x;               // 0..127

    __shared__ float sg[CC];
    __shared__ float sxs[16];
    __shared__ float sho[HID];
    __shared__ float shi[HID];

    sg[t] = g_gap[n][t];
    if (t < 16) {
        float s = 0.f;
        for (int c = 0; c < CC; ++c) s += g_pool[n][c][t];
        sxs[t] = s * (1.f / CC);
    }
    __syncthreads();

    if (t < HID) {
        float a = b_o1[t];
        float b = b_i1[t];
        for (int c = 0; c < CC; ++c) {
            a += sg[c] * W_o1[c * HID + t];
            b += sg[c] * W_i1[c * HID + t];
        }
        sho[t] = fmaxf(a, 0.f);
        shi[t] = fmaxf(b, 0.f);
    }
    __syncthreads();

    float a = b_o2[t];
    float b = b_i2[t];
#pragma unroll
    for (int j = 0; j < HID; ++j) {
        a += sho[j] * W_o2[j * CC + t];
        b += shi[j] * W_i2[j * CC + t];
    }
    g_co[n][t] = a;
    g_ci[n][t] = b;

    if (t < 9) {
        float s = b_sp[t];
#pragma unroll
        for (int p = 0; p < 16; ++p) s += sxs[p] * W_sp[p * 9 + t];
        g_sp[n][t] = s;
    }
}

// ---------------------------------------------------------------------------
// Kernel C: z[n,h,w] = sum_i ci[n,i] * x[n,i,h,w]
// REVERSE traversal (n, h descending): kA just streamed x and left the
// most-recent ~126MB of it in L2. Reading newest-first turns the LRU
// streaming pathology into ~94% L2 hits; misses land at the tail and evict
// only already-consumed lines.
// grid (H, N) = 4096 blocks, 64 threads = one output row.
// ---------------------------------------------------------------------------
__global__ void kC_chanreduce(const float* __restrict__ x) {
    int h = (HH - 1) - blockIdx.x;
    int n = (NN - 1) - blockIdx.y;
    int w = threadIdx.x;               // 0..63

    __shared__ float sci[CC];
    sci[w]      = g_ci[n][w];
    sci[w + 64] = g_ci[n][w + 64];
    __syncthreads();

    const float* xp = x + ((size_t)n * CC) * (HH * WW) + h * WW + w;
    float acc = 0.f;
#pragma unroll 8
    for (int i = 0; i < CC; ++i)
        acc += sci[i] * xp[(size_t)i * (HH * WW)];
    g_z[n][h][w] = acc;
}

// ---------------------------------------------------------------------------
// Fused kernel DE: per block (row-chunk, n, o-group):
//   1) stage z rows [r0-1, r0+8] in smem (L2-hot)
//   2) compute t tile = conv3x3(z, sp) for 8 rows
//   3) sweep this block's 32 output channels with STREAMING stores (out is
//      never re-read; evict-first keeps L2 clean for next iteration's kA)
// grid (8, NN, 4) = 2048 blocks, 256 threads.
// ---------------------------------------------------------------------------
__global__ void kDE_convscale(float4* __restrict__ out) {
    int chunk = blockIdx.x;            // 0..7 -> output rows [chunk*8, +8)
    int n     = blockIdx.y;
    int ogrp  = blockIdx.z;            // 0..3 -> o in [ogrp*32, +32)
    int t     = threadIdx.x;           // 0..255

    __shared__ float sz[10][WW];       // rows r0-1 .. r0+8
    __shared__ float st[8][WW];        // conv result tile
    __shared__ float sco[32];
    __shared__ float ssp[9];

    int r0 = chunk * 8;

    if (t < 160) {
        int rr = t >> 4, qq = t & 15;
        int h = r0 - 1 + rr;
        float4 v = make_float4(0.f, 0.f, 0.f, 0.f);
        if (h >= 0 && h < HH)
            v = ((const float4*)g_z)[(n * HH + h) * 16 + qq];
        ((float4*)&sz[rr][0])[qq] = v;
    }
    if (t >= 192 && t < 224) sco[t - 192] = g_co[n][ogrp * 32 + (t - 192)];
    if (t >= 240 && t < 249) ssp[t - 240] = g_sp[n][t - 240];
    __syncthreads();

#pragma unroll
    for (int k = 0; k < 2; ++k) {
        int p = t + k * 256;           // 0..511
        int h = p >> 6, w = p & 63;    // local row 0..7
        float acc = 0.f;
#pragma unroll
        for (int kh = 0; kh < 3; ++kh) {
#pragma unroll
            for (int kw = 0; kw < 3; ++kw) {
                int ww = w + kw - 1;
                if (ww >= 0 && ww < WW)
                    acc += ssp[kh * 3 + kw] * sz[h + kh][ww];
            }
        }
        st[h][w] = acc;
    }
    __syncthreads();

    int q  = t & 127;                  // quad within tile
    int os = t >> 7;                   // 0 or 1 -> 16-channel subgroup
    float4 v = ((const float4*)st)[q];
    int rr = q >> 4, qq = q & 15;

    int o0 = ogrp * 32 + os * 16;
    size_t base = ((size_t)n * CC + o0) * (HH * WW / 4)
                + (size_t)(r0 + rr) * 16 + qq;
#pragma unroll 4
    for (int o = 0; o < 16; ++o) {
        float s = sco[os * 16 + o];
        float4 ov;
        ov.x = v.x * s; ov.y = v.y * s; ov.z = v.z * s; ov.w = v.w * s;
        __stcs(&out[base + (size_t)o * (HH * WW / 4)], ov);
    }
}

// ---------------------------------------------------------------------------
extern "C" void kernel_launch(void* const* d_in, const int* in_sizes, int n_in,
                              void* d_out, int out_size) {
    const float* x    = (const float*)d_in[0];
    const float* W_sp = (const float*)d_in[1];
    const float* b_sp = (const float*)d_in[2];
    const float* W_o1 = (const float*)d_in[3];
    const float* b_o1 = (const float*)d_in[4];
    const float* W_o2 = (const float*)d_in[5];
    const float* b_o2 = (const float*)d_in[6];
    const float* W_i1 = (const float*)d_in[7];
    const float* b_i1 = (const float*)d_in[8];
    const float* W_i2 = (const float*)d_in[9];
    const float* b_i2 = (const float*)d_in[10];

    kA_reduce<<<NN * CC, 256>>>(x);
    kB_mlp<<<NN, CC>>>(W_sp, b_sp, W_o1, b_o1, W_o2, b_o2,
                       W_i1, b_i1, W_i2, b_i2);
    {
        dim3 g(HH, NN);
        kC_chanreduce<<<g, WW>>>(x);
    }
    {
        dim3 g(8, NN, 4);
        kDE_convscale<<<g, 256>>>((float4*)d_out);
    }
}